// round 6
// baseline (speedup 1.0000x reference)
#include <cuda_runtime.h>
#include <cuda_fp16.h>
#include <math.h>

#define NN   100000
#define NE   800000
#define FIN  128
#define C    32
#define D    16
#define CST  1e-5f

// ---------- persistent scratch (device globals; no allocation allowed) ----------
__device__ float  g_Q[NN * C];                         // 12.8 MB
__device__ __align__(16) __half g_KV0[NN * 64];        // 12.8 MB: 32 K + 16 V + 16 pad per node (128B row)
__device__ __align__(16) __half g_Kh[2][NN * C];       // 2 x 6.4 MB  (K1, K2)
__device__ __align__(16) __half g_Mh[2][NN * C * D];   // 2 x 102.4 MB (row = 512 halfs)
__device__ int    g_deg[NN];
__device__ int    g_off[NN + 1];
__device__ int    g_cur[NN];
__device__ int    g_adj[NE];
__device__ int    g_bsum[1024];
__device__ int    g_bpre[1024];
__device__ int    g_is64;

// ------------------------------------------------- edge dtype detection -------
__global__ void detect_kernel(const void* __restrict__ ei, int n) {
    const long long* p = (const long long*)ei;
    int ok = 1;
    for (int i = 0; i < 16; i++) {
        long long v = p[i];
        if (v < 0 || v >= (long long)n) ok = 0;
    }
    g_is64 = ok;
}

// ---------------------------------------------------------------- CSR build ---
__global__ void zero_deg_kernel(int n) {
    for (int i = blockIdx.x * blockDim.x + threadIdx.x; i < n; i += gridDim.x * blockDim.x)
        g_deg[i] = 0;
}

__global__ void count_kernel(const void* __restrict__ ei, int ne) {
    const long long* p64 = (const long long*)ei;
    const int*       p32 = (const int*)ei;
    int is64 = g_is64;
    for (int e = blockIdx.x * blockDim.x + threadIdx.x; e < ne; e += gridDim.x * blockDim.x) {
        int c = is64 ? (int)p64[ne + e] : p32[ne + e];
        atomicAdd(&g_deg[c], 1);
    }
}

__global__ void scanA_kernel(int n) {
    int i    = blockIdx.x * 256 + threadIdx.x;
    int lane = threadIdx.x & 31, w = threadIdx.x >> 5;
    int v = (i < n) ? g_deg[i] : 0;
    int s = v;
#pragma unroll
    for (int o = 1; o < 32; o <<= 1) {
        int t = __shfl_up_sync(0xffffffffu, s, o);
        if (lane >= o) s += t;
    }
    __shared__ int ws[8], wo[8];
    if (lane == 31) ws[w] = s;
    __syncthreads();
    if (threadIdx.x == 0) {
        int run = 0;
#pragma unroll
        for (int k = 0; k < 8; k++) { wo[k] = run; run += ws[k]; }
        g_bsum[blockIdx.x] = run;
    }
    __syncthreads();
    if (i < n) g_off[i] = s - v + wo[w];
}

__global__ void scanB_kernel(int nb, int n) {
    __shared__ int s[1024];
    int tid = threadIdx.x;
    int v = (tid < nb) ? g_bsum[tid] : 0;
    s[tid] = v;
    __syncthreads();
    for (int o = 1; o < 1024; o <<= 1) {
        int t = (tid >= o) ? s[tid - o] : 0;
        __syncthreads();
        s[tid] += t;
        __syncthreads();
    }
    if (tid < nb) g_bpre[tid] = s[tid] - v;
    if (tid == 1023) g_off[n] = s[1023];
}

__global__ void scanC_kernel(int n) {
    int i = blockIdx.x * 256 + threadIdx.x;
    if (i < n) {
        int o = g_off[i] + g_bpre[blockIdx.x];
        g_off[i] = o;
        g_cur[i] = o;
    }
}

__global__ void scatter_kernel(const void* __restrict__ ei, int ne) {
    const long long* p64 = (const long long*)ei;
    const int*       p32 = (const int*)ei;
    int is64 = g_is64;
    for (int e = blockIdx.x * blockDim.x + threadIdx.x; e < ne; e += gridDim.x * blockDim.x) {
        int c = is64 ? (int)p64[ne + e] : p32[ne + e];
        int r = is64 ? (int)p64[e]      : p32[e];
        int p = atomicAdd(&g_cur[c], 1);
        g_adj[p] = r;
    }
}

// -------------------------------------------------------- front-end (fused) ---
__global__ void feat_kernel(const float* __restrict__ feat,
                            const float* __restrict__ Win, const float* __restrict__ bin,
                            const float* __restrict__ Wq,  const float* __restrict__ bq,
                            const float* __restrict__ Wk,  const float* __restrict__ bk,
                            const float* __restrict__ Wv,  const float* __restrict__ bv,
                            const float* __restrict__ hopwise,
                            float* __restrict__ out, int n) {
    __shared__ float sWin[FIN * C];
    __shared__ float sWq[C * C], sWk[C * C], sWv[C * D];
    __shared__ float sb[3 * C + D];
    __shared__ float sx [8][FIN];
    __shared__ float sxs[8][C];

    int tid = threadIdx.x;
    for (int i = tid; i < FIN * C; i += 256) sWin[i] = Win[i];
    for (int i = tid; i < C * C;   i += 256) { sWq[i] = Wq[i]; sWk[i] = Wk[i]; }
    for (int i = tid; i < C * D;   i += 256) sWv[i] = Wv[i];
    if (tid < C) { sb[tid] = bin[tid]; sb[C + tid] = bq[tid]; sb[2 * C + tid] = bk[tid]; }
    if (tid < D) sb[3 * C + tid] = bv[tid];
    __syncthreads();

    int w = tid >> 5, lane = tid & 31;
    int node = blockIdx.x * 8 + w;
    if (node >= n) return;

    ((float4*)sx[w])[lane] = ((const float4*)feat)[node * (FIN / 4) + lane];
    __syncwarp();

    float acc = sb[lane];
#pragma unroll 8
    for (int i = 0; i < FIN; i++) acc = fmaf(sx[w][i], sWin[i * C + lane], acc);
    float x = fmaxf(acc, 0.f);
    sxs[w][lane] = x;
    __syncwarp();

    float qz = sb[C + lane], kz = sb[2 * C + lane];
    float vz = (lane < D) ? sb[3 * C + lane] : 0.f;
#pragma unroll
    for (int i = 0; i < C; i++) {
        float xi = sxs[w][i];
        qz = fmaf(xi, sWq[i * C + lane], qz);
        kz = fmaf(xi, sWk[i * C + lane], kz);
        if (lane < D) vz = fmaf(xi, sWv[i * D + lane], vz);
    }
    float q = (qz > 0.f) ? 1.f + qz : expf(qz);  // 1 + elu
    float k = (kz > 0.f) ? 1.f + kz : expf(kz);

    g_Q[node * C + lane] = q;

    __half* kv = &g_KV0[(size_t)node * 64];
    kv[lane] = __float2half_rn(k);
    if (lane < D) kv[32 + lane] = __float2half_rn(vz);
    if (lane < 16) kv[48 + lane] = __half(0.f);

    if (lane < D) out[node * D + lane] = hopwise[0] * vz;
}

// --------------------------------------------------------------- H/C epilogue -
// (hop1 layout: acc float4, thread t covers M[i=t>>2][4g..4g+3], kacc in t<32)
__device__ __forceinline__ void hc_epilogue(float* __restrict__ out, int c,
                                            float hw, float4 acc, float kacc,
                                            int t) {
    int i = t >> 2;
    float qi = g_Q[c * 32 + i];
    float h0 = qi * acc.x, h1 = qi * acc.y, h2 = qi * acc.z, h3 = qi * acc.w;
#pragma unroll
    for (int off = 4; off <= 16; off <<= 1) {
        h0 += __shfl_xor_sync(0xffffffffu, h0, off);
        h1 += __shfl_xor_sync(0xffffffffu, h1, off);
        h2 += __shfl_xor_sync(0xffffffffu, h2, off);
        h3 += __shfl_xor_sync(0xffffffffu, h3, off);
    }
    __shared__ float sH[4][4][4];
    __shared__ float sC;
    int lane = t & 31, w = t >> 5;
    if (lane < 4) { sH[w][lane][0] = h0; sH[w][lane][1] = h1; sH[w][lane][2] = h2; sH[w][lane][3] = h3; }
    if (t < 32) {
        float cp = g_Q[c * 32 + t] * kacc;
#pragma unroll
        for (int off = 16; off >= 1; off >>= 1) cp += __shfl_xor_sync(0xffffffffu, cp, off);
        if (t == 0) sC = cp;
    }
    __syncthreads();
    if (t < 16) {
        float H = sH[0][t >> 2][t & 3] + sH[1][t >> 2][t & 3]
                + sH[2][t >> 2][t & 3] + sH[3][t >> 2][t & 3];
        out[c * 16 + t] += hw * H / (sC + CST);
    }
}

// ------------------------------------------------------------- hop 1 (rank-1) -
// Stage each neighbor's 128B KV row into double-buffered SMEM via 8 LDG.128,
// then all 128 threads build K(x)V from broadcast LDS. Minimal LDG count.
__global__ void hop1_kernel(float* __restrict__ out,
                            const float* __restrict__ hopwise) {
    __shared__ __align__(16) __half skv[2][64];
    int c = blockIdx.x;
    int t = threadIdx.x;
    int i = t >> 2, g4 = t & 3;
    int start = g_off[c], end = g_off[c + 1];

    float4 acc = make_float4(0.f, 0.f, 0.f, 0.f);
    float  kacc = 0.f;

    if (start < end && t < 8) {
        int r = g_adj[start];
        ((uint4*)skv[0])[t] = ((const uint4*)&g_KV0[(size_t)r * 64])[t];
    }
    __syncthreads();

    for (int e = start; e < end; e++) {
        int buf = (e - start) & 1;
        if (e + 1 < end && t < 8) {
            int r = g_adj[e + 1];
            ((uint4*)skv[buf ^ 1])[t] = ((const uint4*)&g_KV0[(size_t)r * 64])[t];
        }
        float k = __half2float(skv[buf][i]);
        float2 a = __half22float2(*(const __half2*)&skv[buf][32 + 4 * g4]);
        float2 b = __half22float2(*(const __half2*)&skv[buf][32 + 4 * g4 + 2]);
        acc.x = fmaf(k, a.x, acc.x);
        acc.y = fmaf(k, a.y, acc.y);
        acc.z = fmaf(k, b.x, acc.z);
        acc.w = fmaf(k, b.y, acc.w);
        if (t < 32) kacc += __half2float(skv[buf][t]);
        __syncthreads();
    }

    // write M1 (uint2/thread) + K1
    {
        __half2 ha = __floats2half2_rn(acc.x, acc.y);
        __half2 hb = __floats2half2_rn(acc.z, acc.w);
        uint2 o; o.x = *(unsigned*)&ha; o.y = *(unsigned*)&hb;
        __stcs(&((uint2*)g_Mh[0])[(size_t)c * 128 + t], o);
        if (t < 32) {
            __half hk = __float2half_rn(kacc);
            __stcs((unsigned short*)&g_Kh[0][c * 32 + t], *(unsigned short*)&hk);
        }
    }
    hc_epilogue(out, c, hopwise[1], acc, kacc, t);
}

// ------------------------------------------------------------- hops 2 & 3 -----
// uint4 gather: 64 threads cover a 1KB M row; two groups (g = t>>6) process
// alternating edges. Thread s owns halfs 8s..8s+7 (i = s>>1, j in (s&1)*8..+8).
__global__ void hop_kernel(float* __restrict__ out,
                           const float* __restrict__ hopwise,
                           int hop, int src, int writeM) {
    const uint4*  __restrict__ Mold = (const uint4*)g_Mh[src];
    uint4*        __restrict__ Mnew = (uint4*)g_Mh[src ^ 1];
    const __half* __restrict__ Kold = g_Kh[src];
    __half*       __restrict__ Knew = g_Kh[src ^ 1];

    int c = blockIdx.x;
    int t = threadIdx.x;        // 0..127
    int g = t >> 6;             // edge-parity group
    int s = t & 63;             // uint4 slot
    int start = g_off[c], end = g_off[c + 1];

    float acc[8];
#pragma unroll
    for (int j = 0; j < 8; j++) acc[j] = 0.f;
    float kx = 0.f, ky = 0.f;

    for (int e = start + g; e < end; e += 2) {
        int r = g_adj[e];
        uint4 u = Mold[(size_t)r * 64 + s];
        float2 p0 = __half22float2(*reinterpret_cast<const __half2*>(&u.x));
        float2 p1 = __half22float2(*reinterpret_cast<const __half2*>(&u.y));
        float2 p2 = __half22float2(*reinterpret_cast<const __half2*>(&u.z));
        float2 p3 = __half22float2(*reinterpret_cast<const __half2*>(&u.w));
        acc[0] += p0.x; acc[1] += p0.y; acc[2] += p1.x; acc[3] += p1.y;
        acc[4] += p2.x; acc[5] += p2.y; acc[6] += p3.x; acc[7] += p3.y;
        if (s < 16) {
            float2 kf = __half22float2(*(const __half2*)&Kold[r * 32 + 2 * s]);
            kx += kf.x; ky += kf.y;
        }
    }

    // combine groups
    __shared__ float  sAcc[64][8];
    __shared__ float2 sKc[16];
    if (g == 1) {
#pragma unroll
        for (int j = 0; j < 8; j++) sAcc[s][j] = acc[j];
        if (s < 16) sKc[s] = make_float2(kx, ky);
    }
    __syncthreads();

    __shared__ float sH[2][2][8];
    __shared__ float sCv;

    if (g == 0) {
#pragma unroll
        for (int j = 0; j < 8; j++) acc[j] += sAcc[s][j];
        if (s < 16) { kx += sKc[s].x; ky += sKc[s].y; }

        if (writeM) {
            __half2 h0 = __floats2half2_rn(acc[0], acc[1]);
            __half2 h1 = __floats2half2_rn(acc[2], acc[3]);
            __half2 h2 = __floats2half2_rn(acc[4], acc[5]);
            __half2 h3 = __floats2half2_rn(acc[6], acc[7]);
            uint4 o;
            o.x = *(unsigned*)&h0; o.y = *(unsigned*)&h1;
            o.z = *(unsigned*)&h2; o.w = *(unsigned*)&h3;
            __stcs(&Mnew[(size_t)c * 64 + s], o);
            if (s < 16) {
                __half2 kk = __floats2half2_rn(kx, ky);
                __stcs((unsigned*)&Knew[c * 32 + 2 * s], *(unsigned*)&kk);
            }
        }

        // H: reduce q_i * acc over i within each warp (16 i's), keep jh = s&1
        int i = s >> 1;
        float qi = g_Q[c * 32 + i];
        float h[8];
#pragma unroll
        for (int j = 0; j < 8; j++) h[j] = qi * acc[j];
#pragma unroll
        for (int off = 2; off <= 16; off <<= 1) {
#pragma unroll
            for (int j = 0; j < 8; j++) h[j] += __shfl_xor_sync(0xffffffffu, h[j], off);
        }
        int lane = t & 31, w = t >> 5;   // w in {0,1}
        if (lane < 2) {
#pragma unroll
            for (int j = 0; j < 8; j++) sH[w][lane][j] = h[j];
        }
        // C: lanes 0..15 of warp 0 hold K pairs (i = 2s, 2s+1)
        if (s < 16) {
            float cp = g_Q[c * 32 + 2 * s] * kx + g_Q[c * 32 + 2 * s + 1] * ky;
#pragma unroll
            for (int off = 1; off <= 8; off <<= 1)
                cp += __shfl_xor_sync(0x0000ffffu, cp, off);
            if (s == 0) sCv = cp;
        }
    }
    __syncthreads();

    if (t < 16) {
        float H = sH[0][t >> 3][t & 7] + sH[1][t >> 3][t & 7];
        out[c * 16 + t] += hopwise[hop + 1] * H / (sCv + CST);
    }
}

// ------------------------------------------------------------------ launch ----
extern "C" void kernel_launch(void* const* d_in, const int* in_sizes, int n_in,
                              void* d_out, int out_size) {
    const float* feat    = (const float*)d_in[0];
    const void*  ei      = d_in[1];
    const float* Win     = (const float*)d_in[2];
    const float* bin     = (const float*)d_in[3];
    const float* Wq      = (const float*)d_in[4];
    const float* bq      = (const float*)d_in[5];
    const float* Wk      = (const float*)d_in[6];
    const float* bk      = (const float*)d_in[7];
    const float* Wv      = (const float*)d_in[8];
    const float* bv      = (const float*)d_in[9];
    const float* hopwise = (const float*)d_in[10];
    float*       out     = (float*)d_out;

    int n  = in_sizes[0] / FIN;   // 100000
    int ne = in_sizes[1] / 2;     // 800000
    int nb = (n + 255) / 256;

    detect_kernel<<<1, 1>>>(ei, n);
    zero_deg_kernel<<<256, 256>>>(n);
    count_kernel<<<1024, 256>>>(ei, ne);
    scanA_kernel<<<nb, 256>>>(n);
    scanB_kernel<<<1, 1024>>>(nb, n);
    scanC_kernel<<<nb, 256>>>(n);
    scatter_kernel<<<1024, 256>>>(ei, ne);

    feat_kernel<<<(n + 7) / 8, 256>>>(feat, Win, bin, Wq, bq, Wk, bk, Wv, bv,
                                      hopwise, out, n);

    hop1_kernel<<<n, 128>>>(out, hopwise);
    hop_kernel<<<n, 128>>>(out, hopwise, 1, 0, 1);
    hop_kernel<<<n, 128>>>(out, hopwise, 2, 1, 0);
}

// round 7
// speedup vs baseline: 1.0612x; 1.0612x over previous
#include <cuda_runtime.h>
#include <cuda_fp16.h>
#include <math.h>

#define NN   100000
#define NE   800000
#define FIN  128
#define C    32
#define D    16
#define CST  1e-5f

// ---------- persistent scratch (device globals; no allocation allowed) ----------
__device__ float  g_Q[NN * C];                         // 12.8 MB
__device__ __align__(16) __half g_KV0[NN * 64];        // 12.8 MB: 32 K + 16 V + 16 pad (128B row)
__device__ __align__(16) __half g_Kh[2][NN * C];       // 2 x 6.4 MB  (K1, K2)
__device__ __align__(16) __half g_Mh[2][NN * C * D];   // 2 x 102.4 MB (row = 512 halfs)
__device__ int    g_deg[NN];
__device__ int    g_off[NN + 1];
__device__ int    g_cur[NN];
__device__ int    g_adj[NE];

// ---------------------------------------------- inline edge dtype detection ---
// All 32 lanes read one of the first 16 int64 values (128B, in-bounds for both
// layouts). int64 data: all in [0,n). int32 read as int64: high word = next
// index, nonzero w.h.p. Warp-uniform result.
__device__ __forceinline__ int edge_is64(const void* __restrict__ ei, int n) {
    const long long* p = (const long long*)ei;
    long long v = p[threadIdx.x & 15];
    return __all_sync(0xffffffffu, v >= 0 && v < (long long)n);
}

// ----------------------------------------- front-end + edge count (fused) -----
// Edge counting (1 edge per thread, grid covers NE) + per-node transform:
// x = relu(feat@Win+bin); Q = 1+elu(x@Wq+bq); K = 1+elu(x@Wk+bk); V = x@Wv+bv
// Store Q fp32, (K|V) packed fp16 per node. No M0 materialization (rank-1).
__global__ void featcount_kernel(const float* __restrict__ feat,
                                 const void*  __restrict__ ei, int ne,
                                 const float* __restrict__ Win, const float* __restrict__ bin,
                                 const float* __restrict__ Wq,  const float* __restrict__ bq,
                                 const float* __restrict__ Wk,  const float* __restrict__ bk,
                                 const float* __restrict__ Wv,  const float* __restrict__ bv,
                                 const float* __restrict__ hopwise,
                                 float* __restrict__ out, int n) {
    // --- edge degree count (g_deg pre-zeroed by memset) ---
    int gtid = blockIdx.x * 256 + threadIdx.x;
    int is64 = edge_is64(ei, n);
    if (gtid < ne) {
        int c = is64 ? (int)((const long long*)ei)[ne + gtid]
                     : ((const int*)ei)[ne + gtid];
        atomicAdd(&g_deg[c], 1);
    }

    // --- stage weights ---
    __shared__ float sWin[FIN * C];
    __shared__ float sWq[C * C], sWk[C * C], sWv[C * D];
    __shared__ float sb[3 * C + D];
    __shared__ float sx [8][FIN];
    __shared__ float sxs[8][C];

    int tid = threadIdx.x;
    for (int i = tid; i < FIN * C; i += 256) sWin[i] = Win[i];
    for (int i = tid; i < C * C;   i += 256) { sWq[i] = Wq[i]; sWk[i] = Wk[i]; }
    for (int i = tid; i < C * D;   i += 256) sWv[i] = Wv[i];
    if (tid < C) { sb[tid] = bin[tid]; sb[C + tid] = bq[tid]; sb[2 * C + tid] = bk[tid]; }
    if (tid < D) sb[3 * C + tid] = bv[tid];
    __syncthreads();

    int w = tid >> 5, lane = tid & 31;
    int node = blockIdx.x * 8 + w;
    if (node >= n) return;

    ((float4*)sx[w])[lane] = ((const float4*)feat)[node * (FIN / 4) + lane];
    __syncwarp();

    float acc = sb[lane];
#pragma unroll 8
    for (int i = 0; i < FIN; i++) acc = fmaf(sx[w][i], sWin[i * C + lane], acc);
    float x = fmaxf(acc, 0.f);
    sxs[w][lane] = x;
    __syncwarp();

    float qz = sb[C + lane], kz = sb[2 * C + lane];
    float vz = (lane < D) ? sb[3 * C + lane] : 0.f;
#pragma unroll
    for (int i = 0; i < C; i++) {
        float xi = sxs[w][i];
        qz = fmaf(xi, sWq[i * C + lane], qz);
        kz = fmaf(xi, sWk[i * C + lane], kz);
        if (lane < D) vz = fmaf(xi, sWv[i * D + lane], vz);
    }
    float q = (qz > 0.f) ? 1.f + qz : expf(qz);  // 1 + elu
    float k = (kz > 0.f) ? 1.f + kz : expf(kz);

    g_Q[node * C + lane] = q;

    __half* kv = &g_KV0[(size_t)node * 64];
    kv[lane] = __float2half_rn(k);
    if (lane < D) kv[32 + lane] = __float2half_rn(vz);
    if (lane < 16) kv[48 + lane] = __half(0.f);

    if (lane < D) out[node * D + lane] = hopwise[0] * vz;
}

// --------------------------- single-block tiled exclusive scan (coalesced) ----
__global__ void scan1_kernel(int n) {
    __shared__ int wsum[32];
    __shared__ int carry;
    int tid = threadIdx.x, lane = tid & 31, w = tid >> 5;
    if (tid == 0) carry = 0;
    __syncthreads();
    for (int base = 0; base < n; base += 1024) {
        int i = base + tid;
        int v = (i < n) ? g_deg[i] : 0;
        int s = v;
#pragma unroll
        for (int o = 1; o < 32; o <<= 1) {
            int t = __shfl_up_sync(0xffffffffu, s, o);
            if (lane >= o) s += t;
        }
        if (lane == 31) wsum[w] = s;
        __syncthreads();
        if (w == 0) {
            int ws = wsum[lane];
#pragma unroll
            for (int o = 1; o < 32; o <<= 1) {
                int t = __shfl_up_sync(0xffffffffu, ws, o);
                if (lane >= o) ws += t;
            }
            wsum[lane] = ws;
        }
        __syncthreads();
        int pre   = (w ? wsum[w - 1] : 0);
        int total = wsum[31];               // read before sync(3): safe vs next tile
        int excl  = carry + pre + s - v;
        if (i < n) { g_off[i] = excl; g_cur[i] = excl; }
        __syncthreads();
        if (tid == 0) carry += total;
    }
    if (tid == 0) g_off[n] = carry;
}

__global__ void scatter_kernel(const void* __restrict__ ei, int ne, int n) {
    const long long* p64 = (const long long*)ei;
    const int*       p32 = (const int*)ei;
    int is64 = edge_is64(ei, n);
    for (int e = blockIdx.x * blockDim.x + threadIdx.x; e < ne; e += gridDim.x * blockDim.x) {
        int c = is64 ? (int)p64[ne + e] : p32[ne + e];
        int r = is64 ? (int)p64[e]      : p32[e];
        int p = atomicAdd(&g_cur[c], 1);
        g_adj[p] = r;
    }
}

// --------------------------------------------------------------- H/C epilogue -
__device__ __forceinline__ void hc_epilogue(float* __restrict__ out, int c,
                                            float hw, float4 acc, float kacc,
                                            int t) {
    int i = t >> 2;
    float qi = g_Q[c * 32 + i];
    float h0 = qi * acc.x, h1 = qi * acc.y, h2 = qi * acc.z, h3 = qi * acc.w;
#pragma unroll
    for (int off = 4; off <= 16; off <<= 1) {
        h0 += __shfl_xor_sync(0xffffffffu, h0, off);
        h1 += __shfl_xor_sync(0xffffffffu, h1, off);
        h2 += __shfl_xor_sync(0xffffffffu, h2, off);
        h3 += __shfl_xor_sync(0xffffffffu, h3, off);
    }
    __shared__ float sH[4][4][4];
    __shared__ float sC;
    int lane = t & 31, w = t >> 5;
    if (lane < 4) { sH[w][lane][0] = h0; sH[w][lane][1] = h1; sH[w][lane][2] = h2; sH[w][lane][3] = h3; }
    if (t < 32) {
        float cp = g_Q[c * 32 + t] * kacc;
#pragma unroll
        for (int off = 16; off >= 1; off >>= 1) cp += __shfl_xor_sync(0xffffffffu, cp, off);
        if (t == 0) sC = cp;
    }
    __syncthreads();
    if (t < 16) {
        float H = sH[0][t >> 2][t & 3] + sH[1][t >> 2][t & 3]
                + sH[2][t >> 2][t & 3] + sH[3][t >> 2][t & 3];
        out[c * 16 + t] += hw * H / (sC + CST);
    }
}

// ------------------------------------------------------------- hop 1 (rank-1) -
// M1[c] = sum K0[r] (x) V0[r] from 96B factor rows (L2-resident). R5 version.
__global__ void hop1_kernel(float* __restrict__ out,
                            const float* __restrict__ hopwise) {
    int c = blockIdx.x;
    int t = threadIdx.x;
    int i = t >> 2, g4 = t & 3;
    int start = g_off[c], end = g_off[c + 1];

    float4 acc = make_float4(0.f, 0.f, 0.f, 0.f);
    float  kacc = 0.f;

    int e = start;
    for (; e + 1 < end; e += 2) {
        int r0 = g_adj[e], r1 = g_adj[e + 1];
        const __half* kv0 = &g_KV0[(size_t)r0 * 64];
        const __half* kv1 = &g_KV0[(size_t)r1 * 64];
        float k0 = __half2float(kv0[i]);
        float k1 = __half2float(kv1[i]);
        uint2 uv0 = *(const uint2*)&kv0[32 + 4 * g4];
        uint2 uv1 = *(const uint2*)&kv1[32 + 4 * g4];
        float2 a0 = __half22float2(*(const __half2*)&uv0.x);
        float2 b0 = __half22float2(*(const __half2*)&uv0.y);
        float2 a1 = __half22float2(*(const __half2*)&uv1.x);
        float2 b1 = __half22float2(*(const __half2*)&uv1.y);
        acc.x = fmaf(k0, a0.x, fmaf(k1, a1.x, acc.x));
        acc.y = fmaf(k0, a0.y, fmaf(k1, a1.y, acc.y));
        acc.z = fmaf(k0, b0.x, fmaf(k1, b1.x, acc.z));
        acc.w = fmaf(k0, b0.y, fmaf(k1, b1.y, acc.w));
        if (t < 32) kacc += __half2float(kv0[t]) + __half2float(kv1[t]);
    }
    if (e < end) {
        int r0 = g_adj[e];
        const __half* kv0 = &g_KV0[(size_t)r0 * 64];
        float k0 = __half2float(kv0[i]);
        uint2 uv0 = *(const uint2*)&kv0[32 + 4 * g4];
        float2 a0 = __half22float2(*(const __half2*)&uv0.x);
        float2 b0 = __half22float2(*(const __half2*)&uv0.y);
        acc.x = fmaf(k0, a0.x, acc.x);
        acc.y = fmaf(k0, a0.y, acc.y);
        acc.z = fmaf(k0, b0.x, acc.z);
        acc.w = fmaf(k0, b0.y, acc.w);
        if (t < 32) kacc += __half2float(kv0[t]);
    }

    {
        __half2 ha = __floats2half2_rn(acc.x, acc.y);
        __half2 hb = __floats2half2_rn(acc.z, acc.w);
        uint2 o; o.x = *(unsigned*)&ha; o.y = *(unsigned*)&hb;
        __stcs(&((uint2*)g_Mh[0])[(size_t)c * 128 + t], o);
        if (t < 32) {
            __half hk = __float2half_rn(kacc);
            __stcs((unsigned short*)&g_Kh[0][c * 32 + t], *(unsigned short*)&hk);
        }
    }
    hc_epilogue(out, c, hopwise[1], acc, kacc, t);
}

// ------------------------------------------------------------- hops 2 & 3 -----
// uint2 gather over full fp16 M rows, 2-edge unroll. R5 version.
__global__ void hop_kernel(float* __restrict__ out,
                           const float* __restrict__ hopwise,
                           int hop, int src, int writeM) {
    const uint2*  __restrict__ Mold = (const uint2*)g_Mh[src];
    uint2*        __restrict__ Mnew = (uint2*)g_Mh[src ^ 1];
    const __half* __restrict__ Kold = g_Kh[src];
    __half*       __restrict__ Knew = g_Kh[src ^ 1];

    int c = blockIdx.x;
    int t = threadIdx.x;
    int start = g_off[c], end = g_off[c + 1];

    float4 acc = make_float4(0.f, 0.f, 0.f, 0.f);
    float  kacc = 0.f;

    int e = start;
    for (; e + 1 < end; e += 2) {
        int r0 = g_adj[e], r1 = g_adj[e + 1];
        uint2 u0 = Mold[(size_t)r0 * 128 + t];
        uint2 u1 = Mold[(size_t)r1 * 128 + t];
        float2 a0 = __half22float2(*(const __half2*)&u0.x);
        float2 b0 = __half22float2(*(const __half2*)&u0.y);
        float2 a1 = __half22float2(*(const __half2*)&u1.x);
        float2 b1 = __half22float2(*(const __half2*)&u1.y);
        acc.x += a0.x + a1.x; acc.y += a0.y + a1.y;
        acc.z += b0.x + b1.x; acc.w += b0.y + b1.y;
        if (t < 32) kacc += __half2float(Kold[r0 * 32 + t]) + __half2float(Kold[r1 * 32 + t]);
    }
    if (e < end) {
        int r0 = g_adj[e];
        uint2 u0 = Mold[(size_t)r0 * 128 + t];
        float2 a0 = __half22float2(*(const __half2*)&u0.x);
        float2 b0 = __half22float2(*(const __half2*)&u0.y);
        acc.x += a0.x; acc.y += a0.y; acc.z += b0.x; acc.w += b0.y;
        if (t < 32) kacc += __half2float(Kold[r0 * 32 + t]);
    }

    if (writeM) {
        __half2 ha = __floats2half2_rn(acc.x, acc.y);
        __half2 hb = __floats2half2_rn(acc.z, acc.w);
        uint2 o; o.x = *(unsigned*)&ha; o.y = *(unsigned*)&hb;
        __stcs(&Mnew[(size_t)c * 128 + t], o);
        if (t < 32) {
            __half hk = __float2half_rn(kacc);
            __stcs((unsigned short*)&Knew[c * 32 + t], *(unsigned short*)&hk);
        }
    }
    hc_epilogue(out, c, hopwise[hop + 1], acc, kacc, t);
}

// ------------------------------------------------------------------ launch ----
extern "C" void kernel_launch(void* const* d_in, const int* in_sizes, int n_in,
                              void* d_out, int out_size) {
    const float* feat    = (const float*)d_in[0];
    const void*  ei      = d_in[1];
    const float* Win     = (const float*)d_in[2];
    const float* bin     = (const float*)d_in[3];
    const float* Wq      = (const float*)d_in[4];
    const float* bq      = (const float*)d_in[5];
    const float* Wk      = (const float*)d_in[6];
    const float* bk      = (const float*)d_in[7];
    const float* Wv      = (const float*)d_in[8];
    const float* bv      = (const float*)d_in[9];
    const float* hopwise = (const float*)d_in[10];
    float*       out     = (float*)d_out;

    int n  = in_sizes[0] / FIN;   // 100000
    int ne = in_sizes[1] / 2;     // 800000

    void* degp = nullptr;
    cudaGetSymbolAddress(&degp, g_deg);
    cudaMemsetAsync(degp, 0, NN * sizeof(int));

    // launch #1: fused feat + edge count
    featcount_kernel<<<(n + 7) / 8, 256>>>(feat, ei, ne, Win, bin, Wq, bq,
                                           Wk, bk, Wv, bv, hopwise, out, n);
    // #2: scan, #3: scatter
    scan1_kernel<<<1, 1024>>>(n);
    scatter_kernel<<<1024, 256>>>(ei, ne, n);

    // #4..#6: hops (ncu -s 5 -c 1 lands on #4 = hop1)
    hop1_kernel<<<n, 128>>>(out, hopwise);
    hop_kernel<<<n, 128>>>(out, hopwise, 1, 0, 1);
    hop_kernel<<<n, 128>>>(out, hopwise, 2, 1, 0);
}